// round 4
// baseline (speedup 1.0000x reference)
#include <cuda_runtime.h>
#include <cuda_bf16.h>

// ---------------------------------------------------------------------------
// TuckER scorer, GB300.
// Inputs (metadata order):
//  0 E   (100000,200) f32      7 bn0_gamma (200)
//  1 R1  (3,30)                8 bn0_beta  (200)
//  2 R2  (5,30)                9 bn1_gamma (200)
//  3 R3  (3,80)               10 bn1_beta  (200)
//  4 W1  (30,20100)           11 e1_idx (1024) i32
//  5 W2  (30,19900)           12 r_idx  (1024) i32
//  6 W3  (20,200,200)
// out: (1024,100000) f32 sigmoid scores
// ---------------------------------------------------------------------------

#define D1 200
#define BATCH 1024
#define NENT 100000
#define NREL 11
#define KDIM 80   // DS+DA+DO = 30+30+20

__constant__ int c_perm[NREL] = {8, 0, 3, 9, 4, 5, 6, 7, 1, 10, 2};

// scratch (device globals; no allocation allowed)
__device__ float g_R[NREL * KDIM];          // assembled relation matrix
__device__ float g_M[NREL * D1 * D1];       // per-relation mixing matrix (1.76 MB)
__device__ float g_x0[BATCH * D1];          // gathered + BN0
__device__ float g_x1[BATCH * D1];          // after M contraction
__device__ float g_xn[BATCH * D1];          // after BN1

// ---------------------------------------------------------------------------
// K1: assemble R (11 x 80) with zero-padded blocks
__global__ void build_R_kernel(const float* __restrict__ R1,
                               const float* __restrict__ R2,
                               const float* __restrict__ R3) {
    int t = blockIdx.x * blockDim.x + threadIdx.x;
    if (t >= NREL * KDIM) return;
    int row = t / KDIM, c = t % KDIM;
    float v = 0.f;
    if (row < 3) {                       // symmetric rels: [R1 | 0]
        if (c < 30) v = R1[row * 30 + c];
    } else if (row < 8) {                // antisym rels: [0 | R2 | 0]
        if (c >= 30 && c < 60) v = R2[(row - 3) * 30 + (c - 30)];
    } else {                             // free rels: R3 full
        v = R3[(row - 8) * KDIM + c];
    }
    g_R[t] = v;
}

// ---------------------------------------------------------------------------
// K2: M[rel][j][k] = sum_i R[rel,i] * W[i,j,k] using closed-form index maps.
// One block per (rel, j); thread = k.
__global__ void build_M_kernel(const float* __restrict__ W1,
                               const float* __restrict__ W2,
                               const float* __restrict__ W3) {
    int blk = blockIdx.x;
    int rel = blk / D1;
    int j   = blk % D1;
    __shared__ float r[KDIM];
    if (threadIdx.x < KDIM) r[threadIdx.x] = g_R[rel * KDIM + threadIdx.x];
    __syncthreads();
    int k = threadIdx.x;
    if (k >= D1) return;

    float acc = 0.f;
    // symmetric block: sym_index[j,k] = tri(min) + |j-k|, tri(m)=(401-m)*m/2
    {
        int m = min(j, k), d = abs(j - k);
        int sidx = ((2 * D1 - m + 1) * m) / 2 + d;
        #pragma unroll 5
        for (int i = 0; i < 30; i++)
            acc += r[i] * W1[i * 20100 + sidx];
    }
    // antisymmetric block
    if (j != k) {
        int jj = min(j, k), kk = max(j, k);
        int aidx = ((2 * D1 - jj - 1) * jj) / 2 + (kk - jj) - 1;  // into W2
        float sgn = (j < k) ? 1.f : -1.f;
        float s2 = 0.f;
        #pragma unroll 5
        for (int i = 0; i < 30; i++)
            s2 += r[30 + i] * W2[i * 19900 + aidx];
        acc += sgn * s2;
    }
    // free block
    #pragma unroll 5
    for (int i = 0; i < 20; i++)
        acc += r[60 + i] * W3[i * D1 * D1 + j * D1 + k];

    g_M[rel * D1 * D1 + j * D1 + k] = acc;
}

// ---------------------------------------------------------------------------
// K3: gather + BatchNorm0 (training-mode batch stats over the 1024 gathered rows)
// One block per feature j; 256 threads reduce over batch.
__global__ void bn0_kernel(const float* __restrict__ E, const int* __restrict__ e1,
                           const float* __restrict__ gamma, const float* __restrict__ beta) {
    int j = blockIdx.x;
    int tid = threadIdx.x;
    float v[4];
    float s = 0.f, sq = 0.f;
    #pragma unroll
    for (int t = 0; t < 4; t++) {
        int b = t * 256 + tid;
        float x = E[(long long)e1[b] * D1 + j];
        v[t] = x; s += x; sq += x * x;
    }
    __shared__ float sh0[256], sh1[256];
    sh0[tid] = s; sh1[tid] = sq; __syncthreads();
    for (int o = 128; o > 0; o >>= 1) {
        if (tid < o) { sh0[tid] += sh0[tid + o]; sh1[tid] += sh1[tid + o]; }
        __syncthreads();
    }
    __shared__ float scale_s, shift_s;
    if (tid == 0) {
        float mean = sh0[0] * (1.f / BATCH);
        float var  = sh1[0] * (1.f / BATCH) - mean * mean;
        float rs = rsqrtf(var + 1e-5f);
        float sc = rs * gamma[j];
        scale_s = sc;
        shift_s = beta[j] - mean * sc;
    }
    __syncthreads();
    float sc = scale_s, sf = shift_s;
    #pragma unroll
    for (int t = 0; t < 4; t++)
        g_x0[(t * 256 + tid) * D1 + j] = v[t] * sc + sf;
}

// ---------------------------------------------------------------------------
// K4: x1[b,k] = sum_j M[rel(b)][j][k] * x0[b,j]. One block per batch element.
__global__ void apply_M_kernel(const int* __restrict__ r_idx) {
    int b = blockIdx.x;
    __shared__ float xs[D1];
    int tid = threadIdx.x;
    if (tid < D1) xs[tid] = g_x0[b * D1 + tid];
    __syncthreads();
    if (tid >= D1) return;
    int rel = c_perm[r_idx[b]];
    const float* Mr = g_M + rel * D1 * D1;
    float acc = 0.f;
    #pragma unroll 8
    for (int jj = 0; jj < D1; jj++)
        acc += Mr[jj * D1 + tid] * xs[jj];
    g_x1[b * D1 + tid] = acc;
}

// ---------------------------------------------------------------------------
// K5: BatchNorm1 on x1 -> xn
__global__ void bn1_kernel(const float* __restrict__ gamma, const float* __restrict__ beta) {
    int j = blockIdx.x;
    int tid = threadIdx.x;
    float v[4];
    float s = 0.f, sq = 0.f;
    #pragma unroll
    for (int t = 0; t < 4; t++) {
        float x = g_x1[(t * 256 + tid) * D1 + j];
        v[t] = x; s += x; sq += x * x;
    }
    __shared__ float sh0[256], sh1[256];
    sh0[tid] = s; sh1[tid] = sq; __syncthreads();
    for (int o = 128; o > 0; o >>= 1) {
        if (tid < o) { sh0[tid] += sh0[tid + o]; sh1[tid] += sh1[tid + o]; }
        __syncthreads();
    }
    __shared__ float scale_s, shift_s;
    if (tid == 0) {
        float mean = sh0[0] * (1.f / BATCH);
        float var  = sh1[0] * (1.f / BATCH) - mean * mean;
        float rs = rsqrtf(var + 1e-5f);
        float sc = rs * gamma[j];
        scale_s = sc;
        shift_s = beta[j] - mean * sc;
    }
    __syncthreads();
    float sc = scale_s, sf = shift_s;
    #pragma unroll
    for (int t = 0; t < 4; t++)
        g_xn[(t * 256 + tid) * D1 + j] = v[t] * sc + sf;
}

// ---------------------------------------------------------------------------
// K6: scores = sigmoid(xn @ E^T). M=1024, N=100000, K=200.
// 128x128 tile, BK=8, 256 threads, 8x8 micro-tile with packed fma.rn.f32x2
// accumulators (8 rows x 4 float2 column-pairs, pairs strided by 32 cols for
// conflict-free LDS.64 and coalesced float2 stores).
__global__ __launch_bounds__(256) void gemm_sig_kernel(const float* __restrict__ E,
                                                       float* __restrict__ out) {
    __shared__ __align__(16) float As[8][128];
    __shared__ __align__(16) float Bs[8][128];
    const int NN = NENT;
    int bn0 = blockIdx.x * 128;
    int bm0 = blockIdx.y * 128;
    int tid = threadIdx.x;
    int tx = tid & 15, ty = tid >> 4;
    int lr = tid >> 1;           // tile row loaded by this thread
    int lk = (tid & 1) * 4;      // k-offset (0 or 4)

    unsigned long long acc[8][4];
    #pragma unroll
    for (int i = 0; i < 8; i++)
        #pragma unroll
        for (int p = 0; p < 4; p++) acc[i][p] = 0ull;

    const float* xptr = g_xn + (bm0 + lr) * D1 + lk;
    int er = bn0 + lr;
    const float* eptr = E + (long long)er * D1 + lk;
    bool evalid = er < NN;

    for (int k0 = 0; k0 < D1; k0 += 8) {
        float4 xa = *(const float4*)(xptr + k0);
        float4 eb = make_float4(0.f, 0.f, 0.f, 0.f);
        if (evalid) eb = *(const float4*)(eptr + k0);
        __syncthreads();
        As[lk + 0][lr] = xa.x; As[lk + 1][lr] = xa.y;
        As[lk + 2][lr] = xa.z; As[lk + 3][lr] = xa.w;
        Bs[lk + 0][lr] = eb.x; Bs[lk + 1][lr] = eb.y;
        Bs[lk + 2][lr] = eb.z; Bs[lk + 3][lr] = eb.w;
        __syncthreads();
        #pragma unroll
        for (int kk = 0; kk < 8; kk++) {
            float a[8];
            *(float4*)(a)     = *(const float4*)(&As[kk][ty * 8]);
            *(float4*)(a + 4) = *(const float4*)(&As[kk][ty * 8 + 4]);
            unsigned long long b2[4];
            #pragma unroll
            for (int p = 0; p < 4; p++)
                b2[p] = *(const unsigned long long*)(&Bs[kk][tx * 2 + 32 * p]);
            #pragma unroll
            for (int i = 0; i < 8; i++) {
                unsigned long long a2;
                asm("mov.b64 %0, {%1, %1};" : "=l"(a2) : "f"(a[i]));
                #pragma unroll
                for (int p = 0; p < 4; p++)
                    asm("fma.rn.f32x2 %0, %1, %2, %0;"
                        : "+l"(acc[i][p]) : "l"(a2), "l"(b2[p]));
            }
        }
    }

    #pragma unroll
    for (int i = 0; i < 8; i++) {
        int row = bm0 + ty * 8 + i;
        #pragma unroll
        for (int p = 0; p < 4; p++) {
            int col = bn0 + tx * 2 + 32 * p;
            if (col < NN) {    // NN even, col even -> pair wholly valid or not
                float lo = __uint_as_float((unsigned)(acc[i][p] & 0xffffffffull));
                float hi = __uint_as_float((unsigned)(acc[i][p] >> 32));
                float2 o;
                o.x = 1.f / (1.f + __expf(-lo));
                o.y = 1.f / (1.f + __expf(-hi));
                *(float2*)(out + (long long)row * NN + col) = o;
            }
        }
    }
}

// ---------------------------------------------------------------------------
extern "C" void kernel_launch(void* const* d_in, const int* in_sizes, int n_in,
                              void* d_out, int out_size) {
    const float* E   = (const float*)d_in[0];
    const float* R1  = (const float*)d_in[1];
    const float* R2  = (const float*)d_in[2];
    const float* R3  = (const float*)d_in[3];
    const float* W1  = (const float*)d_in[4];
    const float* W2  = (const float*)d_in[5];
    const float* W3  = (const float*)d_in[6];
    const float* g0  = (const float*)d_in[7];
    const float* b0  = (const float*)d_in[8];
    const float* g1  = (const float*)d_in[9];
    const float* b1  = (const float*)d_in[10];
    const int*   e1  = (const int*)d_in[11];
    const int*   rix = (const int*)d_in[12];
    float* out = (float*)d_out;

    build_R_kernel<<<4, 256>>>(R1, R2, R3);
    build_M_kernel<<<NREL * D1, 256>>>(W1, W2, W3);
    bn0_kernel<<<D1, 256>>>(E, e1, g0, b0);
    apply_M_kernel<<<BATCH, 256>>>(rix);
    bn1_kernel<<<D1, 256>>>(g1, b1);
    dim3 grid((NENT + 127) / 128, BATCH / 128);
    gemm_sig_kernel<<<grid, 256>>>(E, out);
}

// round 11
// speedup vs baseline: 1.4854x; 1.4854x over previous
#include <cuda_runtime.h>
#include <cuda_bf16.h>
#include <cstdint>

// ---------------------------------------------------------------------------
// TuckER scorer, GB300 — legacy tensor-core round (mma.sync bf16; tcgen05 is
// feature-gated off under the harness's compute_103 virtual arch).
//  scores = sigmoid( BN1( BN0(E[e1]) @ M[rel] ) @ E^T )
// Split precision: s = x_hi*e_hi + x_hi*e_lo + x_lo*e_hi  (K packed to 640)
// ---------------------------------------------------------------------------

#define D1 200
#define BATCH 1024
#define NENT 100000
#define NROWS_PAD 100096          // 782 tiles * 128
#define NREL 11
#define KDIM 80
#define KP 640                    // packed K: 200+200+200 (+40 zero pad)
#define NCH 10                    // K chunks of 64
#define CSTRIDE 132               // epilogue stage stride (132*4 % 16 == 0)
#define GEMM_SMEM 67584           // max(65536 mainloop, 132*128*4 epilogue)

__constant__ int c_perm[NREL] = {8, 0, 3, 9, 4, 5, 6, 7, 1, 10, 2};

__device__ float g_R[NREL * KDIM];
__device__ float g_M[NREL * D1 * D1];
__device__ float g_x0[BATCH * D1];
__device__ float g_x1[BATCH * D1];
__device__ __nv_bfloat16 g_Apack[BATCH * KP];                    // [x_hi|x_hi|x_lo|0]
__device__ __nv_bfloat16 g_Epack[(long long)NROWS_PAD * KP];     // [e_hi|e_lo|e_hi|0]

// ---------------- helpers ----------------
__device__ __forceinline__ uint32_t smem_u32(const void* p) {
    uint32_t a;
    asm("{ .reg .u64 t; cvta.to.shared.u64 t, %1; cvt.u32.u64 %0, t; }" : "=r"(a) : "l"(p));
    return a;
}
__device__ __forceinline__ uint32_t swz128(uint32_t x) { return x ^ ((x >> 3) & 0x70); }

#define CP16(sa, ga) asm volatile("cp.async.cg.shared.global [%0], [%1], 16;" :: "r"(sa), "l"(ga) : "memory")
#define LDSM_X4(r0, r1, r2, r3, a) asm volatile( \
    "ldmatrix.sync.aligned.m8n8.x4.shared.b16 {%0,%1,%2,%3}, [%4];" \
    : "=r"(r0), "=r"(r1), "=r"(r2), "=r"(r3) : "r"(a))
#define MMA16816(c0, c1, c2, c3, a0, a1, a2, a3, b0, b1) asm volatile( \
    "mma.sync.aligned.m16n8k16.row.col.f32.bf16.bf16.f32 " \
    "{%0,%1,%2,%3}, {%4,%5,%6,%7}, {%8,%9}, {%0,%1,%2,%3};" \
    : "+f"(c0), "+f"(c1), "+f"(c2), "+f"(c3) \
    : "r"(a0), "r"(a1), "r"(a2), "r"(a3), "r"(b0), "r"(b1))

// ---------------------------------------------------------------------------
// K1: assemble R (11 x 80)
__global__ void build_R_kernel(const float* __restrict__ R1, const float* __restrict__ R2,
                               const float* __restrict__ R3) {
    int t = blockIdx.x * blockDim.x + threadIdx.x;
    if (t >= NREL * KDIM) return;
    int row = t / KDIM, c = t % KDIM;
    float v = 0.f;
    if (row < 3)       { if (c < 30) v = R1[row * 30 + c]; }
    else if (row < 8)  { if (c >= 30 && c < 60) v = R2[(row - 3) * 30 + (c - 30)]; }
    else               { v = R3[(row - 8) * KDIM + c]; }
    g_R[t] = v;
}

// K2: M[rel][j][k] via closed-form index maps
__global__ void build_M_kernel(const float* __restrict__ W1, const float* __restrict__ W2,
                               const float* __restrict__ W3) {
    int rel = blockIdx.x / D1, j = blockIdx.x % D1;
    __shared__ float r[KDIM];
    if (threadIdx.x < KDIM) r[threadIdx.x] = g_R[rel * KDIM + threadIdx.x];
    __syncthreads();
    int k = threadIdx.x;
    if (k >= D1) return;
    float acc = 0.f;
    {
        int m = min(j, k), d = abs(j - k);
        int sidx = ((2 * D1 - m + 1) * m) / 2 + d;
        #pragma unroll 5
        for (int i = 0; i < 30; i++) acc += r[i] * W1[i * 20100 + sidx];
    }
    if (j != k) {
        int jj = min(j, k), kk = max(j, k);
        int aidx = ((2 * D1 - jj - 1) * jj) / 2 + (kk - jj) - 1;
        float sgn = (j < k) ? 1.f : -1.f, s2 = 0.f;
        #pragma unroll 5
        for (int i = 0; i < 30; i++) s2 += r[30 + i] * W2[i * 19900 + aidx];
        acc += sgn * s2;
    }
    #pragma unroll 5
    for (int i = 0; i < 20; i++) acc += r[60 + i] * W3[i * D1 * D1 + j * D1 + k];
    g_M[rel * D1 * D1 + j * D1 + k] = acc;
}

// K3: gather + BN0
__global__ void bn0_kernel(const float* __restrict__ E, const int* __restrict__ e1,
                           const float* __restrict__ gamma, const float* __restrict__ beta) {
    int j = blockIdx.x, tid = threadIdx.x;
    float v[4], s = 0.f, sq = 0.f;
    #pragma unroll
    for (int t = 0; t < 4; t++) {
        float x = E[(long long)e1[t * 256 + tid] * D1 + j];
        v[t] = x; s += x; sq += x * x;
    }
    __shared__ float sh0[256], sh1[256];
    sh0[tid] = s; sh1[tid] = sq; __syncthreads();
    for (int o = 128; o > 0; o >>= 1) {
        if (tid < o) { sh0[tid] += sh0[tid + o]; sh1[tid] += sh1[tid + o]; }
        __syncthreads();
    }
    __shared__ float scale_s, shift_s;
    if (tid == 0) {
        float mean = sh0[0] * (1.f / BATCH);
        float var  = sh1[0] * (1.f / BATCH) - mean * mean;
        float sc = rsqrtf(var + 1e-5f) * gamma[j];
        scale_s = sc; shift_s = beta[j] - mean * sc;
    }
    __syncthreads();
    float sc = scale_s, sf = shift_s;
    #pragma unroll
    for (int t = 0; t < 4; t++) g_x0[(t * 256 + tid) * D1 + j] = v[t] * sc + sf;
}

// K4: x1 = x0 @ M[rel]
__global__ void apply_M_kernel(const int* __restrict__ r_idx) {
    int b = blockIdx.x, tid = threadIdx.x;
    __shared__ float xs[D1];
    if (tid < D1) xs[tid] = g_x0[b * D1 + tid];
    __syncthreads();
    if (tid >= D1) return;
    const float* Mr = g_M + c_perm[r_idx[b]] * D1 * D1;
    float acc = 0.f;
    #pragma unroll 8
    for (int jj = 0; jj < D1; jj++) acc += Mr[jj * D1 + tid] * xs[jj];
    g_x1[b * D1 + tid] = acc;
}

// K5: BN1 fused with A-pack (bf16 hi/lo split)
__global__ void bn1_pack_kernel(const float* __restrict__ gamma, const float* __restrict__ beta) {
    int j = blockIdx.x, tid = threadIdx.x;
    float v[4], s = 0.f, sq = 0.f;
    #pragma unroll
    for (int t = 0; t < 4; t++) {
        float x = g_x1[(t * 256 + tid) * D1 + j];
        v[t] = x; s += x; sq += x * x;
    }
    __shared__ float sh0[256], sh1[256];
    sh0[tid] = s; sh1[tid] = sq; __syncthreads();
    for (int o = 128; o > 0; o >>= 1) {
        if (tid < o) { sh0[tid] += sh0[tid + o]; sh1[tid] += sh1[tid + o]; }
        __syncthreads();
    }
    __shared__ float scale_s, shift_s;
    if (tid == 0) {
        float mean = sh0[0] * (1.f / BATCH);
        float var  = sh1[0] * (1.f / BATCH) - mean * mean;
        float sc = rsqrtf(var + 1e-5f) * gamma[j];
        scale_s = sc; shift_s = beta[j] - mean * sc;
    }
    __syncthreads();
    float sc = scale_s, sf = shift_s;
    #pragma unroll
    for (int t = 0; t < 4; t++) {
        int b = t * 256 + tid;
        float x = v[t] * sc + sf;
        __nv_bfloat16 h = __float2bfloat16(x);
        __nv_bfloat16 l = __float2bfloat16(x - __bfloat162float(h));
        g_Apack[b * KP + j]       = h;
        g_Apack[b * KP + 200 + j] = h;
        g_Apack[b * KP + 400 + j] = l;
    }
}

// K5b: zero pad cols [600,640) of A-pack
__global__ void zero_tailA_kernel() {
    int t = blockIdx.x * blockDim.x + threadIdx.x;
    if (t < BATCH * 40) {
        int b = t / 40, c = 600 + t % 40;
        g_Apack[b * KP + c] = __float2bfloat16(0.f);
    }
}

// K6: pack E -> [e_hi | e_lo | e_hi | 0], rows padded to 100096 with zeros
__global__ void pack_E_kernel(const float* __restrict__ E) {
    long long gid = (long long)blockIdx.x * 256 + threadIdx.x;  // NROWS_PAD*80
    int row = (int)(gid / 80), cg = (int)(gid % 80);
    int c0 = cg * 8;
    __align__(16) __nv_bfloat16 o[8];
    if (row < NENT && c0 < 600) {
        const float* er = E + (long long)row * D1;
        #pragma unroll
        for (int k = 0; k < 8; k++) {
            int c = c0 + k;
            float v; __nv_bfloat16 r;
            if (c < 200)      { v = er[c];       r = __float2bfloat16(v); }
            else if (c < 400) { v = er[c - 200]; __nv_bfloat16 h = __float2bfloat16(v);
                                r = __float2bfloat16(v - __bfloat162float(h)); }
            else              { v = er[c - 400]; r = __float2bfloat16(v); }
            o[k] = r;
        }
    } else {
        #pragma unroll
        for (int k = 0; k < 8; k++) o[k] = __float2bfloat16(0.f);
    }
    *(uint4*)(&g_Epack[(long long)row * KP + c0]) = *(const uint4*)o;
}

// ---------------------------------------------------------------------------
// K7: mma.sync bf16 GEMM + sigmoid. CTA 128x128, 8 warps (2x4), warp 64x32.
// BK=64 double-buffered cp.async; SW128 smem; K=640 in 10 chunks.
__global__ __launch_bounds__(256) void gemm_mma_kernel(float* __restrict__ out) {
    extern __shared__ char dyn_smem[];
    int tid = threadIdx.x, wid = tid >> 5, lane = tid & 31;
    int warp_m = wid >> 2, warp_n = wid & 3;     // 2 x 4
    int m0 = blockIdx.x * 128;
    long long n0 = (long long)blockIdx.y * 128;

    uint32_t base = smem_u32(dyn_smem);          // dyn smem is 1024-aligned
    uint32_t sA[2] = { base,          base + 16384u };
    uint32_t sB[2] = { base + 32768u, base + 49152u };

    const __nv_bfloat16* Ag = g_Apack + (long long)m0 * KP;
    const __nv_bfloat16* Bg = g_Epack + n0 * KP;

    // chunk loader: 128 rows x 64 bf16 (16KB) each for A and B
    auto load_chunk = [&](int c) {
        uint32_t dA = sA[c & 1], dB = sB[c & 1];
        const __nv_bfloat16* ac = Ag + c * 64;
        const __nv_bfloat16* bc = Bg + c * 64;
        #pragma unroll
        for (int v = 0; v < 4; v++) {
            int u = v * 256 + tid;               // 1024 total 16B chunks
            int row = u >> 3, seg = u & 7;
            uint32_t so = swz128((uint32_t)(row * 128 + seg * 16));
            CP16(dA + so, (const char*)(ac + (long long)row * KP + seg * 8));
            CP16(dB + so, (const char*)(bc + (long long)row * KP + seg * 8));
        }
        asm volatile("cp.async.commit_group;" ::: "memory");
    };

    // fragment address lane constants
    int a_row = lane & 15, a_colb = (lane >> 4) * 16;               // bytes
    int b_row = (lane & 7) + ((lane >> 4) << 3);                    // n within 16
    int b_colb = ((lane >> 3) & 1) * 16;                            // bytes

    float acc[4][4][4];
    #pragma unroll
    for (int i = 0; i < 4; i++)
        #pragma unroll
        for (int j = 0; j < 4; j++)
            #pragma unroll
            for (int q = 0; q < 4; q++) acc[i][j][q] = 0.f;

    load_chunk(0);
    load_chunk(1);

    for (int c = 0; c < NCH; c++) {
        if (c < NCH - 1) asm volatile("cp.async.wait_group 1;" ::: "memory");
        else             asm volatile("cp.async.wait_group 0;" ::: "memory");
        __syncthreads();
        uint32_t bufA = sA[c & 1], bufB = sB[c & 1];
        #pragma unroll
        for (int ks = 0; ks < 4; ks++) {
            uint32_t a[4][4], b[2][4];
            #pragma unroll
            for (int mf = 0; mf < 4; mf++) {
                uint32_t off = swz128((uint32_t)((warp_m * 64 + mf * 16 + a_row) * 128
                                                 + ks * 32 + a_colb));
                LDSM_X4(a[mf][0], a[mf][1], a[mf][2], a[mf][3], bufA + off);
            }
            #pragma unroll
            for (int np = 0; np < 2; np++) {
                uint32_t off = swz128((uint32_t)((warp_n * 32 + np * 16 + b_row) * 128
                                                 + ks * 32 + b_colb));
                LDSM_X4(b[np][0], b[np][1], b[np][2], b[np][3], bufB + off);
            }
            #pragma unroll
            for (int mf = 0; mf < 4; mf++) {
                #pragma unroll
                for (int np = 0; np < 2; np++) {
                    MMA16816(acc[mf][np*2][0], acc[mf][np*2][1], acc[mf][np*2][2], acc[mf][np*2][3],
                             a[mf][0], a[mf][1], a[mf][2], a[mf][3], b[np][0], b[np][1]);
                    MMA16816(acc[mf][np*2+1][0], acc[mf][np*2+1][1], acc[mf][np*2+1][2], acc[mf][np*2+1][3],
                             a[mf][0], a[mf][1], a[mf][2], a[mf][3], b[np][2], b[np][3]);
                }
            }
        }
        __syncthreads();
        if (c + 2 < NCH) load_chunk(c + 2);
    }

    // epilogue: stage C in smem (stride 132 -> every row 16B aligned)
    float* sC = (float*)dyn_smem;
    int qr = lane >> 2, qc = (lane & 3) * 2;
    #pragma unroll
    for (int mf = 0; mf < 4; mf++) {
        #pragma unroll
        for (int nf = 0; nf < 4; nf++) {
            int r0 = warp_m * 64 + mf * 16 + qr;
            int cc = warp_n * 32 + nf * 8 + qc;
            *(float2*)&sC[r0 * CSTRIDE + cc]       = make_float2(acc[mf][nf][0], acc[mf][nf][1]);
            *(float2*)&sC[(r0 + 8) * CSTRIDE + cc] = make_float2(acc[mf][nf][2], acc[mf][nf][3]);
        }
    }
    __syncthreads();
    {
        int row = tid >> 1, half = (tid & 1) * 64;
        float* src = &sC[row * CSTRIDE + half];
        float* dst = out + (long long)(m0 + row) * NENT + n0 + half;
        long long cbase = n0 + half;
        #pragma unroll
        for (int v = 0; v < 16; v++) {
            if (cbase + v * 4 + 4 <= NENT) {
                float4 x = *(float4*)(src + v * 4);
                float4 o;
                o.x = 1.f / (1.f + __expf(-x.x));
                o.y = 1.f / (1.f + __expf(-x.y));
                o.z = 1.f / (1.f + __expf(-x.z));
                o.w = 1.f / (1.f + __expf(-x.w));
                *(float4*)(dst + v * 4) = o;
            }
        }
    }
}

// ---------------------------------------------------------------------------
extern "C" void kernel_launch(void* const* d_in, const int* in_sizes, int n_in,
                              void* d_out, int out_size) {
    const float* E   = (const float*)d_in[0];
    const float* R1  = (const float*)d_in[1];
    const float* R2  = (const float*)d_in[2];
    const float* R3  = (const float*)d_in[3];
    const float* W1  = (const float*)d_in[4];
    const float* W2  = (const float*)d_in[5];
    const float* W3  = (const float*)d_in[6];
    const float* g0  = (const float*)d_in[7];
    const float* b0  = (const float*)d_in[8];
    const float* g1  = (const float*)d_in[9];
    const float* b1  = (const float*)d_in[10];
    const int*   e1  = (const int*)d_in[11];
    const int*   rix = (const int*)d_in[12];
    float* out = (float*)d_out;

    cudaFuncSetAttribute(gemm_mma_kernel, cudaFuncAttributeMaxDynamicSharedMemorySize, GEMM_SMEM);

    build_R_kernel<<<4, 256>>>(R1, R2, R3);
    build_M_kernel<<<NREL * D1, 256>>>(W1, W2, W3);
    pack_E_kernel<<<(NROWS_PAD * 80) / 256, 256>>>(E);
    bn0_kernel<<<D1, 256>>>(E, e1, g0, b0);
    apply_M_kernel<<<BATCH, 256>>>(rix);
    bn1_pack_kernel<<<D1, 256>>>(g1, b1);
    zero_tailA_kernel<<<160, 256>>>();

    dim3 grid(BATCH / 128, NROWS_PAD / 128);   // m fastest -> Epack L2 reuse
    gemm_mma_kernel<<<grid, 256, GEMM_SMEM>>>(out);
}